// round 5
// baseline (speedup 1.0000x reference)
#include <cuda_runtime.h>
#include <math.h>

#define NB 32
#define NG 50
#define NA 8400
#define NC 80
#define NCH 85
#define NBLK 33            // ceil(8400/256)
#define NJB 66             // ceil(8400/128) j-blocks for k_assign
#define FLT_BIG 3.402823466e+38f

// -------- scratch (static device globals) --------
__device__ float4 d_box[NB*NA];
__device__ float  d_objl[NB*NA];
__device__ float  d_sobj[NB*NA];
__device__ unsigned long long d_geom[NB*NA];
__device__ unsigned int d_ball[NB*NBLK*8];
__device__ int    d_bcnt[NB*NBLK];
__device__ int    d_nfg[NB];

// compacted (sorted by anchor id)
__device__ int    d_fa[NB*NA];
__device__ float4 d_fbox[NB*NA];
__device__ float  d_fsobj[NB*NA];
__device__ unsigned long long d_fgeom[NB*NA];
__device__ float  d_s[NB*NA];
__device__ float  d_V[NB*NC*NA];                 // [b][c][j] (wanted classes only)
__device__ float2 d_ci[NB*NG*NA];                // (cost, iou)
__device__ float  d_thr[NB*NG];

// partial sums (no atomics; always written)
__device__ double d_obj_part[NB*NBLK];
__device__ double d_as_part[NB*NJB*4];           // iou, obj_corr, cls, num_fg

__device__ __forceinline__ void anchor_info(int a, int& H, float& fs, int& cell) {
    if (a < 6400)      { H = 80; fs = 8.f;  cell = a; }
    else if (a < 8000) { H = 40; fs = 16.f; cell = a - 6400; }
    else               { H = 20; fs = 32.f; cell = a - 8000; }
}
__device__ __forceinline__ const float* lvl_ptr(int a, const float* o0, const float* o1, const float* o2) {
    return a < 6400 ? o0 : (a < 8000 ? o1 : o2);
}
__device__ __forceinline__ double warp_sum(double v) {
    #pragma unroll
    for (int o = 16; o; o >>= 1) v += __shfl_down_sync(0xffffffffu, v, o);
    return v;
}
__device__ __forceinline__ void ins_min(float (&t)[10], float v) {
    #pragma unroll
    for (int i = 0; i < 10; ++i) { if (v < t[i]) { float tmp = t[i]; t[i] = v; v = tmp; } }
}
__device__ __forceinline__ void ins_max(float (&t)[10], float v) {
    #pragma unroll
    for (int i = 0; i < 10; ++i) { if (v > t[i]) { float tmp = t[i]; t[i] = v; v = tmp; } }
}

// -------- K1: decode + geometry (valid gts only) + fg ballots + dense obj BCE --------
__global__ void k_anchor(const float* __restrict__ o0, const float* __restrict__ o1,
                         const float* __restrict__ o2, const float* __restrict__ labels) {
    int b = blockIdx.y, blk = blockIdx.x, tid = threadIdx.x;
    int a = blk*256 + tid;
    __shared__ float Lx[NG], Ly[NG], Lw[NG], Lh[NG];
    __shared__ unsigned char sval[NG];
    __shared__ float Cx[NG], Cy[NG], Cw[NG], Ch[NG];   // compacted valid gts
    __shared__ int  Cg[NG];
    __shared__ int  snv;
    __shared__ int wcnt[8];
    __shared__ double wobj[8];
    if (tid < NG) {
        const float* L = labels + (b*NG + tid)*5;
        float c0 = L[0]; Lx[tid] = L[1]; Ly[tid] = L[2]; Lw[tid] = L[3]; Lh[tid] = L[4];
        sval[tid] = (c0 + Lx[tid] + Ly[tid] + Lw[tid] + Lh[tid]) > 0.f;
    }
    __syncthreads();
    if (tid == 0) {
        int nv = 0;
        for (int g = 0; g < NG; ++g) {
            if (sval[g]) {
                Cx[nv] = Lx[g]; Cy[nv] = Ly[g]; Cw[nv] = Lw[g]; Ch[nv] = Lh[g];
                Cg[nv] = g; nv++;
            }
        }
        snv = nv;
    }
    __syncthreads();
    int nv = snv;

    bool fgany = false;
    double objv = 0.0;
    if (a < NA) {
        int H, cell; float fs;
        anchor_info(a, H, fs, cell);
        const float* o = lvl_ptr(a, o0, o1, o2);
        int chs = H*H;
        int base = b*NCH*chs + cell;
        float v0 = o[base], v1 = o[base+chs], v2 = o[base+2*chs],
              v3 = o[base+3*chs], v4 = o[base+4*chs];
        int x = cell % H, y = cell / H;
        float4 bx;
        bx.x = (v0 + (float)x)*fs;
        bx.y = (v1 + (float)y)*fs;
        bx.z = __expf(v2)*fs;
        bx.w = __expf(v3)*fs;
        int t = b*NA + a;
        d_box[t] = bx;
        d_objl[t] = v4;
        d_sobj[t] = __fdividef(1.f, 1.f + __expf(-v4));
        objv = (double)(fmaxf(v4, 0.f) + __logf(1.f + __expf(-fabsf(v4))));

        float cx = ((float)x + 0.5f)*fs, cy = ((float)y + 0.5f)*fs, rs = 2.5f*fs;
        unsigned long long geom = 0ull;
        for (int k = 0; k < nv; ++k) {
            float gx = Cx[k], gy = Cy[k], gw = Cw[k], gh = Ch[k];
            bool inb = (cx > gx - 0.5f*gw) && (cx < gx + 0.5f*gw) &&
                       (cy > gy - 0.5f*gh) && (cy < gy + 0.5f*gh);
            bool inc = (fabsf(cx - gx) < rs) && (fabsf(cy - gy) < rs);
            if (inb && inc) geom |= 1ull << Cg[k];
            if (inb || inc) fgany = true;
        }
        d_geom[t] = geom;
    }
    unsigned int word = __ballot_sync(0xffffffffu, fgany);
    int w = tid >> 5, lane = tid & 31;
    objv = warp_sum(objv);
    if (lane == 0) {
        d_ball[(b*NBLK + blk)*8 + w] = word;
        wcnt[w] = __popc(word);
        wobj[w] = objv;
    }
    __syncthreads();
    if (tid == 0) {
        int s = 0; double ob = 0.0;
        #pragma unroll
        for (int k = 0; k < 8; ++k) { s += wcnt[k]; ob += wobj[k]; }
        d_bcnt[b*NBLK + blk] = s;
        d_obj_part[b*NBLK + blk] = ob;
    }
}

// -------- K2: globally ordered compaction (+ writes d_nfg) --------
__global__ void k_compact() {
    int b = blockIdx.y, blk = blockIdx.x, tid = threadIdx.x;
    int w = tid >> 5, lane = tid & 31;
    __shared__ int woff[8];
    unsigned int word = d_ball[(b*NBLK + blk)*8 + w];
    if (tid == 0) {
        int s = 0;
        for (int k = 0; k < blk; ++k) s += d_bcnt[b*NBLK + k];
        if (blk == NBLK - 1) d_nfg[b] = s + d_bcnt[b*NBLK + blk];
        int r = s;
        for (int k = 0; k < 8; ++k) {
            woff[k] = r;
            r += __popc(d_ball[(b*NBLK + blk)*8 + k]);
        }
    }
    __syncthreads();
    if ((word >> lane) & 1u) {
        int j = woff[w] + __popc(word & ((1u << lane) - 1u));
        int a = blk*256 + tid;
        int t = b*NA + a;
        int fj = b*NA + j;
        d_fa[fj] = a;
        d_fbox[fj] = d_box[t];
        d_fsobj[fj] = d_sobj[t];
        d_fgeom[fj] = d_geom[t];
    }
}

// -------- K3: per fg anchor: s + V[c] (wanted classes only) --------
__global__ void k_s(const float* __restrict__ o0, const float* __restrict__ o1,
                    const float* __restrict__ o2, const float* __restrict__ labels) {
    int b = blockIdx.y;
    int tid = threadIdx.x;
    int j = blockIdx.x*blockDim.x + tid;
    __shared__ unsigned char swant[NC];
    if (tid < NC) swant[tid] = 0;
    __syncthreads();
    if (tid < NG) {
        const float* L = labels + (b*NG + tid)*5;
        float c0 = L[0];
        if ((c0 + L[1] + L[2] + L[3] + L[4]) > 0.f) swant[(int)c0] = 1;
    }
    __syncthreads();
    if (j >= d_nfg[b]) return;
    int a = d_fa[b*NA + j];
    int H, cell; float fs;
    anchor_info(a, H, fs, cell);
    const float* o = lvl_ptr(a, o0, o1, o2);
    int chs = H*H;
    int base = (b*NCH + 5)*chs + cell;
    float sqs = sqrtf(d_fsobj[b*NA + j]);
    float s = 0.f;
    #pragma unroll 4
    for (int c = 0; c < NC; ++c) {
        float xl = o[base + c*chs];
        float e = __expf(-xl);
        float p = sqs * rsqrtf(1.f + e);
        p = fminf(fmaxf(p, 1e-7f), 1.f - 1e-6f);
        float lm = __logf(1.f - p);
        s += lm;
        if (swant[c])
            d_V[(b*NC + c)*NA + j] = lm - __logf(p);
    }
    d_s[b*NA + j] = s;
}

// -------- K4: fused cost+iou+threshold; ONE WARP PER (b,g) ROW --------
__global__ void k_costthr(const float* __restrict__ labels) {
    int b = blockIdx.y;
    int lane = threadIdx.x & 31, w = threadIdx.x >> 5;
    int g = blockIdx.x*4 + w;
    if (g >= NG) return;
    int gi = b*NG + g;
    const float* L = labels + (size_t)gi*5;
    float c0 = L[0], gx = L[1], gy = L[2], gw = L[3], gh = L[4];
    if ((c0 + gx + gy + gw + gh) <= 0.f) {
        if (lane == 0) d_thr[gi] = -FLT_BIG;
        return;
    }
    int cls = (int)c0;
    float ga = gw*gh;
    float gx0 = gx - 0.5f*gw, gx1 = gx + 0.5f*gw;
    float gy0 = gy - 0.5f*gh, gy1 = gy + 0.5f*gh;
    int n = d_nfg[b];
    int rowbase = gi*NA;
    const float4* fbox = d_fbox + b*NA;
    const float* Vrow = d_V + (b*NC + cls)*NA;
    const float* srow = d_s + b*NA;
    const unsigned long long* grow = d_fgeom + b*NA;

    float ti[10], tc[10];
    #pragma unroll
    for (int i = 0; i < 10; ++i) { ti[i] = 0.f; tc[i] = FLT_BIG; }

    for (int j = lane; j < n; j += 32) {
        float4 bx = fbox[j];
        float px0 = bx.x - 0.5f*bx.z, px1 = bx.x + 0.5f*bx.z;
        float py0 = bx.y - 0.5f*bx.w, py1 = bx.y + 0.5f*bx.w;
        float tlx = fmaxf(gx0, px0), tly = fmaxf(gy0, py0);
        float brx = fminf(gx1, px1), bry = fminf(gy1, py1);
        float en = (tlx < brx && tly < bry) ? 1.f : 0.f;
        float inter = (brx - tlx)*(bry - tly)*en;
        float iou = inter / (ga + bx.z*bx.w - inter + 1e-12f);
        float geomterm = ((grow[j] >> g) & 1ull) ? 0.f : 100000.f;
        float cost = Vrow[j] - srow[j] - 3.f*__logf(iou + 1e-8f) + geomterm;
        float2 ci; ci.x = cost; ci.y = iou;
        d_ci[rowbase + j] = ci;
        if (iou > ti[9]) ins_max(ti, iou);
        if (cost < tc[9]) ins_min(tc, cost);
    }
    // warp tree-merge of top-10 lists
    #pragma unroll
    for (int off = 16; off >= 1; off >>= 1) {
        float ri[10], rc[10];
        #pragma unroll
        for (int i = 0; i < 10; ++i) {
            ri[i] = __shfl_down_sync(0xffffffffu, ti[i], off);
            rc[i] = __shfl_down_sync(0xffffffffu, tc[i], off);
        }
        #pragma unroll
        for (int i = 0; i < 10; ++i) {
            if (ri[i] > ti[9]) ins_max(ti, ri[i]);
            if (rc[i] < tc[9]) ins_min(tc, rc[i]);
        }
    }
    if (lane == 0) {
        float sum = 0.f;
        #pragma unroll
        for (int i = 0; i < 10; ++i) sum += ti[i];
        int dk = (int)sum;
        if (dk < 1) dk = 1;
        if (dk > 10) dk = 10;
        d_thr[gi] = tc[dk - 1];
    }
}

// -------- K5: final match + fg losses (valid gts only; per-block partials) --------
__global__ void k_assign(const float* __restrict__ o0, const float* __restrict__ o1,
                         const float* __restrict__ o2, const float* __restrict__ labels) {
    int b = blockIdx.y;
    int tid = threadIdx.x;
    int j = blockIdx.x*blockDim.x + tid;
    __shared__ float sthr[NG];
    __shared__ int  Cg[NG];
    __shared__ int  snv;
    __shared__ double wpart[4][4];
    if (tid < NG) sthr[tid] = d_thr[b*NG + tid];
    if (tid == 0) {
        int nv = 0;
        for (int g = 0; g < NG; ++g) {
            const float* L = labels + (b*NG + g)*5;
            if ((L[0]+L[1]+L[2]+L[3]+L[4]) > 0.f) Cg[nv++] = g;
        }
        snv = nv;
    }
    __syncthreads();
    int nv = snv;
    double li = 0.0, lo = 0.0, lc = 0.0, lf = 0.0;
    if (j < d_nfg[b]) {
        unsigned long long mmask = 0ull;
        int cnt = 0, bestg = 0;
        float best = FLT_BIG;
        for (int k = 0; k < nv; ++k) {
            int g = Cg[k];
            float c = d_ci[(b*NG + g)*NA + j].x;
            if (c < best) { best = c; bestg = g; }
            if (c <= sthr[g]) { mmask |= 1ull << g; cnt++; }
        }
        if (cnt > 1) mmask &= (1ull << bestg);
        if (mmask) {
            int mgt = __ffsll((long long)mmask) - 1;
            int a = d_fa[b*NA + j];
            float piou = d_ci[(b*NG + mgt)*NA + j].y;
            lf = 1.0;
            lo = -(double)d_objl[b*NA + a];
            const float* L = labels + (b*NG + mgt)*5;
            float tx = L[1], ty = L[2], tw = L[3], th = L[4];
            float4 pb = d_fbox[b*NA + j];
            float tlx = fmaxf(pb.x - 0.5f*pb.z, tx - 0.5f*tw);
            float tly = fmaxf(pb.y - 0.5f*pb.w, ty - 0.5f*th);
            float brx = fminf(pb.x + 0.5f*pb.z, tx + 0.5f*tw);
            float bry = fminf(pb.y + 0.5f*pb.w, ty + 0.5f*th);
            float en = (tlx < brx && tly < bry) ? 1.f : 0.f;
            float iw = fmaxf(brx - tlx, 0.f), ih = fmaxf(bry - tly, 0.f);
            float inter = iw*ih*en;
            float uni = pb.z*pb.w + tw*th - inter + 1e-16f;
            float iou = inter/uni;
            li = (double)(1.f - iou*iou);
            int mcls = (int)L[0];
            int H, cell; float fs;
            anchor_info(a, H, fs, cell);
            const float* o = lvl_ptr(a, o0, o1, o2);
            int chs = H*H;
            int base = (b*NCH + 5)*chs + cell;
            float csum = 0.f;
            #pragma unroll 4
            for (int c = 0; c < NC; ++c) {
                float xl = o[base + c*chs];
                csum += fmaxf(xl, 0.f) + __logf(1.f + __expf(-fabsf(xl)));
            }
            csum -= o[base + mcls*chs] * piou;
            lc = (double)csum;
        }
    }
    li = warp_sum(li); lo = warp_sum(lo); lc = warp_sum(lc); lf = warp_sum(lf);
    int w = tid >> 5;
    if ((tid & 31) == 0) { wpart[w][0] = li; wpart[w][1] = lo; wpart[w][2] = lc; wpart[w][3] = lf; }
    __syncthreads();
    if (tid == 0) {
        double p0 = 0, p1 = 0, p2 = 0, p3 = 0;
        #pragma unroll
        for (int k = 0; k < 4; ++k) { p0 += wpart[k][0]; p1 += wpart[k][1]; p2 += wpart[k][2]; p3 += wpart[k][3]; }
        int pb_ = (b*NJB + blockIdx.x)*4;
        d_as_part[pb_+0] = p0; d_as_part[pb_+1] = p1; d_as_part[pb_+2] = p2; d_as_part[pb_+3] = p3;
    }
}

// -------- K6: reduce partials + combine --------
__global__ void k_final(float* out) {
    int tid = threadIdx.x;
    double li = 0, lob = 0, lc = 0, lf = 0;
    for (int k = tid; k < NB*NJB; k += 256) {
        li  += d_as_part[k*4+0];
        lob += d_as_part[k*4+1];
        lc  += d_as_part[k*4+2];
        lf  += d_as_part[k*4+3];
    }
    for (int k = tid; k < NB*NBLK; k += 256) lob += d_obj_part[k];
    __shared__ double s0[8], s1[8], s2[8], s3[8];
    li = warp_sum(li); lob = warp_sum(lob); lc = warp_sum(lc); lf = warp_sum(lf);
    int w = tid >> 5;
    if ((tid & 31) == 0) { s0[w] = li; s1[w] = lob; s2[w] = lc; s3[w] = lf; }
    __syncthreads();
    if (tid == 0) {
        double a0 = 0, a1 = 0, a2 = 0, a3 = 0;
        #pragma unroll
        for (int k = 0; k < 8; ++k) { a0 += s0[k]; a1 += s1[k]; a2 += s2[k]; a3 += s3[k]; }
        if (a3 < 1.0) a3 = 1.0;
        out[0] = (float)((5.0*a0 + a1 + a2) / a3);
    }
}

extern "C" void kernel_launch(void* const* d_in, const int* in_sizes, int n_in,
                              void* d_out, int out_size) {
    const float* o0 = (const float*)d_in[0];
    const float* o1 = (const float*)d_in[1];
    const float* o2 = (const float*)d_in[2];
    const float* lb = (const float*)d_in[3];

    k_anchor<<<dim3(NBLK, NB), 256>>>(o0, o1, o2, lb);
    k_compact<<<dim3(NBLK, NB), 256>>>();
    k_s<<<dim3(NJB, NB), 128>>>(o0, o1, o2, lb);
    k_costthr<<<dim3((NG + 3)/4, NB), 128>>>(lb);
    k_assign<<<dim3(NJB, NB), 128>>>(o0, o1, o2, lb);
    k_final<<<1, 256>>>((float*)d_out);
}

// round 6
// speedup vs baseline: 1.4165x; 1.4165x over previous
#include <cuda_runtime.h>
#include <math.h>

#define NB 32
#define NG 50
#define NA 8400
#define NC 80
#define NCH 85
#define NBLK 33            // ceil(8400/256)
#define NJB 66             // ceil(8400/128)
#define FLT_BIG 3.402823466e+38f

// -------- scratch --------
__device__ float4 d_box[NB*NA];
__device__ float  d_objl[NB*NA];
__device__ float  d_sobj[NB*NA];
__device__ unsigned long long d_geom[NB*NA];
__device__ unsigned int d_ball[NB*NBLK*8];
__device__ int    d_bcnt[NB*NBLK];
__device__ int    d_nfg[NB];

__device__ int    d_fa[NB*NA];
__device__ float4 d_fbox[NB*NA];
__device__ float  d_fsobj[NB*NA];
__device__ unsigned long long d_fgeom[NB*NA];
__device__ float  d_s[NB*NA];
__device__ float  d_V[NB*NC*NA];
__device__ float2 d_ci[NB*NG*NA];
__device__ float  d_thr[NB*NG];

__device__ double d_obj_part[NB*NBLK];
__device__ double d_as_part[NB*NJB*4];

__device__ __forceinline__ void anchor_info(int a, int& H, float& fs, int& cell) {
    if (a < 6400)      { H = 80; fs = 8.f;  cell = a; }
    else if (a < 8000) { H = 40; fs = 16.f; cell = a - 6400; }
    else               { H = 20; fs = 32.f; cell = a - 8000; }
}
__device__ __forceinline__ const float* lvl_ptr(int a, const float* o0, const float* o1, const float* o2) {
    return a < 6400 ? o0 : (a < 8000 ? o1 : o2);
}
__device__ __forceinline__ double warp_sum(double v) {
    #pragma unroll
    for (int o = 16; o; o >>= 1) v += __shfl_down_sync(0xffffffffu, v, o);
    return v;
}
__device__ __forceinline__ void ins_min(float (&t)[10], float v) {
    #pragma unroll
    for (int i = 0; i < 10; ++i) { if (v < t[i]) { float tmp = t[i]; t[i] = v; v = tmp; } }
}
__device__ __forceinline__ void ins_max(float (&t)[10], float v) {
    #pragma unroll
    for (int i = 0; i < 10; ++i) { if (v > t[i]) { float tmp = t[i]; t[i] = v; v = tmp; } }
}

// -------- K1: decode + geometry (valid gts only) + fg ballots + dense obj BCE --------
__global__ void k_anchor(const float* __restrict__ o0, const float* __restrict__ o1,
                         const float* __restrict__ o2, const float* __restrict__ labels) {
    int b = blockIdx.y, blk = blockIdx.x, tid = threadIdx.x;
    int a = blk*256 + tid;
    __shared__ float Lx[NG], Ly[NG], Lw[NG], Lh[NG];
    __shared__ unsigned char sval[NG];
    __shared__ float Cx[NG], Cy[NG], Cw[NG], Ch[NG];
    __shared__ int  Cg[NG];
    __shared__ int  snv;
    __shared__ int wcnt[8];
    __shared__ double wobj[8];
    if (tid < NG) {
        const float* L = labels + (b*NG + tid)*5;
        float c0 = L[0]; Lx[tid] = L[1]; Ly[tid] = L[2]; Lw[tid] = L[3]; Lh[tid] = L[4];
        sval[tid] = (c0 + Lx[tid] + Ly[tid] + Lw[tid] + Lh[tid]) > 0.f;
    }
    __syncthreads();
    if (tid == 0) {
        int nv = 0;
        for (int g = 0; g < NG; ++g) {
            if (sval[g]) {
                Cx[nv] = Lx[g]; Cy[nv] = Ly[g]; Cw[nv] = Lw[g]; Ch[nv] = Lh[g];
                Cg[nv] = g; nv++;
            }
        }
        snv = nv;
    }
    __syncthreads();
    int nv = snv;

    bool fgany = false;
    double objv = 0.0;
    if (a < NA) {
        int H, cell; float fs;
        anchor_info(a, H, fs, cell);
        const float* o = lvl_ptr(a, o0, o1, o2);
        int chs = H*H;
        int base = b*NCH*chs + cell;
        float v0 = o[base], v1 = o[base+chs], v2 = o[base+2*chs],
              v3 = o[base+3*chs], v4 = o[base+4*chs];
        int x = cell % H, y = cell / H;
        float4 bx;
        bx.x = (v0 + (float)x)*fs;
        bx.y = (v1 + (float)y)*fs;
        bx.z = __expf(v2)*fs;
        bx.w = __expf(v3)*fs;
        int t = b*NA + a;
        d_box[t] = bx;
        d_objl[t] = v4;
        d_sobj[t] = __fdividef(1.f, 1.f + __expf(-v4));
        objv = (double)(fmaxf(v4, 0.f) + __logf(1.f + __expf(-fabsf(v4))));

        float cx = ((float)x + 0.5f)*fs, cy = ((float)y + 0.5f)*fs, rs = 2.5f*fs;
        unsigned long long geom = 0ull;
        for (int k = 0; k < nv; ++k) {
            float gx = Cx[k], gy = Cy[k], gw = Cw[k], gh = Ch[k];
            bool inb = (cx > gx - 0.5f*gw) && (cx < gx + 0.5f*gw) &&
                       (cy > gy - 0.5f*gh) && (cy < gy + 0.5f*gh);
            bool inc = (fabsf(cx - gx) < rs) && (fabsf(cy - gy) < rs);
            if (inb && inc) geom |= 1ull << Cg[k];
            if (inb || inc) fgany = true;
        }
        d_geom[t] = geom;
    }
    unsigned int word = __ballot_sync(0xffffffffu, fgany);
    int w = tid >> 5, lane = tid & 31;
    objv = warp_sum(objv);
    if (lane == 0) {
        d_ball[(b*NBLK + blk)*8 + w] = word;
        wcnt[w] = __popc(word);
        wobj[w] = objv;
    }
    __syncthreads();
    if (tid == 0) {
        int s = 0; double ob = 0.0;
        #pragma unroll
        for (int k = 0; k < 8; ++k) { s += wcnt[k]; ob += wobj[k]; }
        d_bcnt[b*NBLK + blk] = s;
        d_obj_part[b*NBLK + blk] = ob;
    }
}

// -------- K2: globally ordered compaction --------
__global__ void k_compact() {
    int b = blockIdx.y, blk = blockIdx.x, tid = threadIdx.x;
    int w = tid >> 5, lane = tid & 31;
    __shared__ int woff[8];
    unsigned int word = d_ball[(b*NBLK + blk)*8 + w];
    if (tid == 0) {
        int s = 0;
        for (int k = 0; k < blk; ++k) s += d_bcnt[b*NBLK + k];
        if (blk == NBLK - 1) d_nfg[b] = s + d_bcnt[b*NBLK + blk];
        int r = s;
        for (int k = 0; k < 8; ++k) {
            woff[k] = r;
            r += __popc(d_ball[(b*NBLK + blk)*8 + k]);
        }
    }
    __syncthreads();
    if ((word >> lane) & 1u) {
        int j = woff[w] + __popc(word & ((1u << lane) - 1u));
        int a = blk*256 + tid;
        int t = b*NA + a;
        int fj = b*NA + j;
        d_fa[fj] = a;
        d_fbox[fj] = d_box[t];
        d_fsobj[fj] = d_sobj[t];
        d_fgeom[fj] = d_geom[t];
    }
}

// -------- K3: per fg anchor: s + V[c] (wanted classes only) — R2 shape --------
__global__ void k_s(const float* __restrict__ o0, const float* __restrict__ o1,
                    const float* __restrict__ o2, const float* __restrict__ labels) {
    int b = blockIdx.y;
    int tid = threadIdx.x;
    int j = blockIdx.x*blockDim.x + tid;
    __shared__ unsigned char swant[NC];
    if (tid < NC) swant[tid] = 0;
    __syncthreads();
    if (tid < NG) {
        const float* L = labels + (b*NG + tid)*5;
        float c0 = L[0];
        if ((c0 + L[1] + L[2] + L[3] + L[4]) > 0.f) swant[(int)c0] = 1;
    }
    __syncthreads();
    if (j >= d_nfg[b]) return;
    int a = d_fa[b*NA + j];
    int H, cell; float fs;
    anchor_info(a, H, fs, cell);
    const float* o = lvl_ptr(a, o0, o1, o2);
    int chs = H*H;
    int base = (b*NCH + 5)*chs + cell;
    float sqs = sqrtf(d_fsobj[b*NA + j]);
    float s = 0.f;
    #pragma unroll 4
    for (int c = 0; c < NC; ++c) {
        float xl = o[base + c*chs];
        float e = __expf(-xl);
        float p = sqs * rsqrtf(1.f + e);
        p = fminf(fmaxf(p, 1e-7f), 1.f - 1e-6f);
        float lm = __logf(1.f - p);
        s += lm;
        if (swant[c])
            d_V[(b*NC + c)*NA + j] = lm - __logf(p);
    }
    d_s[b*NA + j] = s;
}

// -------- K4: cost + iou matrix — R2 shape (128 thr/row, streaming write) --------
__global__ void k_cost(const float* __restrict__ labels) {
    int b = blockIdx.y, g = blockIdx.x;
    int gi = b*NG + g;
    const float* L = labels + (size_t)gi*5;
    float c0 = L[0], gx = L[1], gy = L[2], gw = L[3], gh = L[4];
    if ((c0 + gx + gy + gw + gh) <= 0.f) return;
    int cls = (int)c0;
    float ga = gw*gh;
    float gx0 = gx - 0.5f*gw, gx1 = gx + 0.5f*gw;
    float gy0 = gy - 0.5f*gh, gy1 = gy + 0.5f*gh;
    int n = d_nfg[b];
    int rowbase = gi*NA;
    const float4* fbox = d_fbox + b*NA;
    const float* Vrow = d_V + (b*NC + cls)*NA;
    const float* srow = d_s + b*NA;
    const unsigned long long* grow = d_fgeom + b*NA;
    for (int j = threadIdx.x; j < n; j += blockDim.x) {
        float4 bx = fbox[j];
        float px0 = bx.x - 0.5f*bx.z, px1 = bx.x + 0.5f*bx.z;
        float py0 = bx.y - 0.5f*bx.w, py1 = bx.y + 0.5f*bx.w;
        float tlx = fmaxf(gx0, px0), tly = fmaxf(gy0, py0);
        float brx = fminf(gx1, px1), bry = fminf(gy1, py1);
        float en = (tlx < brx && tly < bry) ? 1.f : 0.f;
        float inter = (brx - tlx)*(bry - tly)*en;
        float iou = inter / (ga + bx.z*bx.w - inter + 1e-12f);
        float geomterm = ((grow[j] >> g) & 1ull) ? 0.f : 100000.f;
        float cost = Vrow[j] - srow[j] - 3.f*__logf(iou + 1e-8f) + geomterm;
        float2 ci; ci.x = cost; ci.y = iou;
        d_ci[rowbase + j] = ci;
    }
}

// -------- K5: dyn_k + threshold; 64 thr (2 warps) per row, early-reject --------
__global__ void k_thr(const float* __restrict__ labels) {
    int b = blockIdx.y, g = blockIdx.x;
    int gi = b*NG + g;
    int tid = threadIdx.x, lane = tid & 31, w = tid >> 5;
    const float* L = labels + (size_t)gi*5;
    if ((L[0] + L[1] + L[2] + L[3] + L[4]) <= 0.f) {
        if (tid == 0) d_thr[gi] = -FLT_BIG;
        return;
    }
    int n = d_nfg[b];
    float ti[10], tc[10];
    #pragma unroll
    for (int i = 0; i < 10; ++i) { ti[i] = 0.f; tc[i] = FLT_BIG; }
    const float2* row = d_ci + (size_t)gi*NA;
    for (int j = tid; j < n; j += 64) {
        float2 ci = row[j];
        if (ci.y > ti[9]) ins_max(ti, ci.y);
        if (ci.x < tc[9]) ins_min(tc, ci.x);
    }
    #pragma unroll
    for (int off = 16; off >= 1; off >>= 1) {
        float ri[10], rc[10];
        #pragma unroll
        for (int i = 0; i < 10; ++i) {
            ri[i] = __shfl_down_sync(0xffffffffu, ti[i], off);
            rc[i] = __shfl_down_sync(0xffffffffu, tc[i], off);
        }
        #pragma unroll
        for (int i = 0; i < 10; ++i) {
            if (ri[i] > ti[9]) ins_max(ti, ri[i]);
            if (rc[i] < tc[9]) ins_min(tc, rc[i]);
        }
    }
    __shared__ float si[2][10], sc[2][10];
    if (lane == 0) {
        #pragma unroll
        for (int i = 0; i < 10; ++i) { si[w][i] = ti[i]; sc[w][i] = tc[i]; }
    }
    __syncthreads();
    if (tid == 0) {
        #pragma unroll
        for (int i = 0; i < 10; ++i) {
            float v = si[1][i], c = sc[1][i];
            if (v > ti[9]) ins_max(ti, v);
            if (c < tc[9]) ins_min(tc, c);
        }
        float sum = 0.f;
        #pragma unroll
        for (int i = 0; i < 10; ++i) sum += ti[i];
        int dk = (int)sum;
        if (dk < 1) dk = 1;
        if (dk > 10) dk = 10;
        d_thr[gi] = tc[dk - 1];
    }
}

// -------- K6: final match + fg losses (valid gts only; per-block partials) --------
__global__ void k_assign(const float* __restrict__ o0, const float* __restrict__ o1,
                         const float* __restrict__ o2, const float* __restrict__ labels) {
    int b = blockIdx.y;
    int tid = threadIdx.x;
    int j = blockIdx.x*blockDim.x + tid;
    __shared__ float sthr[NG];
    __shared__ int  Cg[NG];
    __shared__ int  snv;
    __shared__ double wpart[4][4];
    if (tid < NG) sthr[tid] = d_thr[b*NG + tid];
    if (tid == 0) {
        int nv = 0;
        for (int g = 0; g < NG; ++g) {
            const float* L = labels + (b*NG + g)*5;
            if ((L[0]+L[1]+L[2]+L[3]+L[4]) > 0.f) Cg[nv++] = g;
        }
        snv = nv;
    }
    __syncthreads();
    int nv = snv;
    double li = 0.0, lo = 0.0, lc = 0.0, lf = 0.0;
    if (j < d_nfg[b]) {
        unsigned long long mmask = 0ull;
        int cnt = 0, bestg = 0;
        float best = FLT_BIG;
        for (int k = 0; k < nv; ++k) {
            int g = Cg[k];
            float c = d_ci[(b*NG + g)*NA + j].x;
            if (c < best) { best = c; bestg = g; }
            if (c <= sthr[g]) { mmask |= 1ull << g; cnt++; }
        }
        if (cnt > 1) mmask &= (1ull << bestg);
        if (mmask) {
            int mgt = __ffsll((long long)mmask) - 1;
            int a = d_fa[b*NA + j];
            float piou = d_ci[(b*NG + mgt)*NA + j].y;
            lf = 1.0;
            lo = -(double)d_objl[b*NA + a];
            const float* L = labels + (b*NG + mgt)*5;
            float tx = L[1], ty = L[2], tw = L[3], th = L[4];
            float4 pb = d_fbox[b*NA + j];
            float tlx = fmaxf(pb.x - 0.5f*pb.z, tx - 0.5f*tw);
            float tly = fmaxf(pb.y - 0.5f*pb.w, ty - 0.5f*th);
            float brx = fminf(pb.x + 0.5f*pb.z, tx + 0.5f*tw);
            float bry = fminf(pb.y + 0.5f*pb.w, ty + 0.5f*th);
            float en = (tlx < brx && tly < bry) ? 1.f : 0.f;
            float iw = fmaxf(brx - tlx, 0.f), ih = fmaxf(bry - tly, 0.f);
            float inter = iw*ih*en;
            float uni = pb.z*pb.w + tw*th - inter + 1e-16f;
            float iou = inter/uni;
            li = (double)(1.f - iou*iou);
            int mcls = (int)L[0];
            int H, cell; float fs;
            anchor_info(a, H, fs, cell);
            const float* o = lvl_ptr(a, o0, o1, o2);
            int chs = H*H;
            int base = (b*NCH + 5)*chs + cell;
            float csum = 0.f;
            #pragma unroll 4
            for (int c = 0; c < NC; ++c) {
                float xl = o[base + c*chs];
                csum += fmaxf(xl, 0.f) + __logf(1.f + __expf(-fabsf(xl)));
            }
            csum -= o[base + mcls*chs] * piou;
            lc = (double)csum;
        }
    }
    li = warp_sum(li); lo = warp_sum(lo); lc = warp_sum(lc); lf = warp_sum(lf);
    int w = tid >> 5;
    if ((tid & 31) == 0) { wpart[w][0] = li; wpart[w][1] = lo; wpart[w][2] = lc; wpart[w][3] = lf; }
    __syncthreads();
    if (tid == 0) {
        double p0 = 0, p1 = 0, p2 = 0, p3 = 0;
        #pragma unroll
        for (int k = 0; k < 4; ++k) { p0 += wpart[k][0]; p1 += wpart[k][1]; p2 += wpart[k][2]; p3 += wpart[k][3]; }
        int pb_ = (b*NJB + blockIdx.x)*4;
        d_as_part[pb_+0] = p0; d_as_part[pb_+1] = p1; d_as_part[pb_+2] = p2; d_as_part[pb_+3] = p3;
    }
}

// -------- K7: reduce partials + combine --------
__global__ void k_final(float* out) {
    int tid = threadIdx.x;
    double li = 0, lob = 0, lc = 0, lf = 0;
    for (int k = tid; k < NB*NJB; k += 256) {
        li  += d_as_part[k*4+0];
        lob += d_as_part[k*4+1];
        lc  += d_as_part[k*4+2];
        lf  += d_as_part[k*4+3];
    }
    for (int k = tid; k < NB*NBLK; k += 256) lob += d_obj_part[k];
    __shared__ double s0[8], s1[8], s2[8], s3[8];
    li = warp_sum(li); lob = warp_sum(lob); lc = warp_sum(lc); lf = warp_sum(lf);
    int w = tid >> 5;
    if ((tid & 31) == 0) { s0[w] = li; s1[w] = lob; s2[w] = lc; s3[w] = lf; }
    __syncthreads();
    if (tid == 0) {
        double a0 = 0, a1 = 0, a2 = 0, a3 = 0;
        #pragma unroll
        for (int k = 0; k < 8; ++k) { a0 += s0[k]; a1 += s1[k]; a2 += s2[k]; a3 += s3[k]; }
        if (a3 < 1.0) a3 = 1.0;
        out[0] = (float)((5.0*a0 + a1 + a2) / a3);
    }
}

extern "C" void kernel_launch(void* const* d_in, const int* in_sizes, int n_in,
                              void* d_out, int out_size) {
    const float* o0 = (const float*)d_in[0];
    const float* o1 = (const float*)d_in[1];
    const float* o2 = (const float*)d_in[2];
    const float* lb = (const float*)d_in[3];

    k_anchor<<<dim3(NBLK, NB), 256>>>(o0, o1, o2, lb);
    k_compact<<<dim3(NBLK, NB), 256>>>();
    k_s<<<dim3(NJB, NB), 128>>>(o0, o1, o2, lb);
    k_cost<<<dim3(NG, NB), 128>>>(lb);
    k_thr<<<dim3(NG, NB), 64>>>(lb);
    k_assign<<<dim3(NJB, NB), 128>>>(o0, o1, o2, lb);
    k_final<<<1, 256>>>((float*)d_out);
}